// round 11
// baseline (speedup 1.0000x reference)
#include <cuda_runtime.h>
#include <cuda_bf16.h>
#include <cstdint>

#define NN 40000
#define NP 40064          // padded: 626 * 64
#define EE 640000
#define HH 128
#define GG 16
#define CC 10

// Scratch (static device globals). 16B aligned.
__device__ __align__(16) __nv_bfloat16 g_pah[NP * HH];  // plane-pair A (hi/lo)
__device__ __align__(16) __nv_bfloat16 g_pal[NP * HH];
__device__ __align__(16) __nv_bfloat16 g_pbh[NP * HH];  // plane-pair B
__device__ __align__(16) __nv_bfloat16 g_pbl[NP * HH];
__device__ __align__(16) __nv_bfloat16 g_gb[NP * HH];   // g = (h@W)*dis, bf16
__device__ __align__(16) float g_dis[NP];               // deg_inv_sqrt (pad stays 0)
__device__ __align__(16) __nv_bfloat16 g_wh[3 * HH * HH];  // W hi, transposed [n][k]
__device__ __align__(16) __nv_bfloat16 g_wl[3 * HH * HH];  // W lo
__device__ int   g_deg[NN];
__device__ int   g_rank[EE];
__device__ int   g_rowptr[NN + 1];
__device__ int   g_col[EE];
__device__ int   g_bsum[64];
__device__ int   g_boff[64];
__device__ __align__(16) float g_pool[GG * HH + GG];

// split two floats into packed bf16x2 hi and lo (lo = residual)
__device__ __forceinline__ void split2(float a, float b, uint32_t& hi, uint32_t& lo) {
    __nv_bfloat16 ah = __float2bfloat16(a);
    __nv_bfloat16 bh = __float2bfloat16(b);
    __nv_bfloat16 al = __float2bfloat16(a - __bfloat162float(ah));
    __nv_bfloat16 bl = __float2bfloat16(b - __bfloat162float(bh));
    hi = (uint32_t)__bfloat16_as_ushort(ah) | ((uint32_t)__bfloat16_as_ushort(bh) << 16);
    lo = (uint32_t)__bfloat16_as_ushort(al) | ((uint32_t)__bfloat16_as_ushort(bl) << 16);
}

__device__ __forceinline__ uint32_t pack_bf2(float a, float b) {
    __nv_bfloat162 t = __floats2bfloat162_rn(a, b);
    return *(uint32_t*)&t;
}

// bf16x2 -> two f32 via bit tricks (alu pipe, no cvt)
__device__ __forceinline__ void acc_u32(float* a, uint32_t u) {
    a[0] += __uint_as_float(u << 16);
    a[1] += __uint_as_float(u & 0xFFFF0000u);
}
__device__ __forceinline__ void acc8(float* a, uint4 v) {
    acc_u32(a + 0, v.x);
    acc_u32(a + 2, v.y);
    acc_u32(a + 4, v.z);
    acc_u32(a + 6, v.w);
}

// ===========================================================================
// CSR build
// ===========================================================================
__global__ void deg_kernel(const int* __restrict__ dst) {
    int e0 = 4 * (blockIdx.x * blockDim.x + threadIdx.x);
#pragma unroll
    for (int j = 0; j < 4; j++) {
        int e = e0 + j;
        if (e < EE) g_rank[e] = atomicAdd(&g_deg[dst[e]], 1);
    }
}

__global__ void scan1_kernel() {
    __shared__ int s[1024];
    int t = threadIdx.x;
    int n = blockIdx.x * 1024 + t;
    int d = (n < NN) ? g_deg[n] : 0;
    s[t] = d;
    __syncthreads();
    for (int off = 1; off < 1024; off <<= 1) {
        int v = (t >= off) ? s[t - off] : 0;
        __syncthreads();
        s[t] += v;
        __syncthreads();
    }
    if (n < NN) g_rowptr[n] = s[t] - d;   // local exclusive
    if (t == 1023) g_bsum[blockIdx.x] = s[t];
}

__global__ void scan2_kernel() {
    __shared__ int s[64];
    int t = threadIdx.x;  // 64
    int v = (t < 40) ? g_bsum[t] : 0;
    s[t] = v;
    __syncthreads();
    for (int off = 1; off < 64; off <<= 1) {
        int u = (t >= off) ? s[t - off] : 0;
        __syncthreads();
        s[t] += u;
        __syncthreads();
    }
    if (t < 40) g_boff[t] = s[t] - v;
}

__global__ void scan3_kernel() {
    int n = blockIdx.x * 1024 + threadIdx.x;
    if (n >= NN) {
        if (n == NN) g_rowptr[NN] = EE;
        return;
    }
    int r = g_rowptr[n] + g_boff[blockIdx.x];
    g_rowptr[n] = r;
    g_dis[n] = rsqrtf((float)g_deg[n] + 1.0f);
}

// Atomic-free fill: pos = rowptr[dst] + rank (rank recorded during deg).
__global__ void fill_kernel(const int* __restrict__ src,
                            const int* __restrict__ dst) {
    int e0 = 4 * (blockIdx.x * blockDim.x + threadIdx.x);
#pragma unroll
    for (int j = 0; j < 4; j++) {
        int e = e0 + j;
        if (e < EE) g_col[g_rowptr[dst[e]] + g_rank[e]] = src[e];
    }
}

// ===========================================================================
// Conversion kernels
// ===========================================================================
__global__ void conv_x_kernel(const float* __restrict__ x) {
    int idx = blockIdx.x * blockDim.x + threadIdx.x;  // 0 .. NP*32-1
    if (idx >= NP * 32) return;
    int row = idx >> 5;
    int q = idx & 31;
    float4 v = (row < NN) ? ((const float4*)x)[(size_t)row * 32 + q]
                          : make_float4(0.f, 0.f, 0.f, 0.f);
    uint32_t h0, l0, h1, l1;
    split2(v.x, v.y, h0, l0);
    split2(v.z, v.w, h1, l1);
    ((uint2*)g_pah)[idx] = make_uint2(h0, h1);
    ((uint2*)g_pal)[idx] = make_uint2(l0, l1);
}

__global__ void conv_w_kernel(const float* __restrict__ W0,
                              const float* __restrict__ W1,
                              const float* __restrict__ W2) {
    const float* W = (blockIdx.y == 0) ? W0 : (blockIdx.y == 1) ? W1 : W2;
    __nv_bfloat16* Wh = g_wh + blockIdx.y * HH * HH;
    __nv_bfloat16* Wl = g_wl + blockIdx.y * HH * HH;
    int idx = blockIdx.x * 256 + threadIdx.x;  // 0..16383
    int k = idx >> 7;
    int n = idx & 127;
    float v = W[k * 128 + n];
    __nv_bfloat16 hi = __float2bfloat16(v);
    __nv_bfloat16 lo = __float2bfloat16(v - __bfloat162float(hi));
    Wh[n * 128 + k] = hi;
    Wl[n * 128 + k] = lo;
}

// ===========================================================================
// HMMA GEMM, 64-row blocks (2 CTAs/SM). 256 thr, 8 warps, warp tile 32x32.
// EPI 0: +bias[col] -> bf16 hi/lo planes.  EPI 1: *dis[row] -> bf16 g.
// ===========================================================================
#define ASTR 272
#define SM_AH 0
#define SM_AL (SM_AH + 64 * ASTR)          // 17408
#define SM_BH (SM_AL + 64 * ASTR)          // 34816
#define SM_BL (SM_BH + 128 * ASTR)         // 69632
#define SM_GEMM_TOTAL (SM_BL + 128 * ASTR) // 104448

__device__ __forceinline__ void mma_bf16(float* c, const uint32_t* a, const uint32_t* b) {
    asm volatile(
        "mma.sync.aligned.m16n8k16.row.col.f32.bf16.bf16.f32 "
        "{%0,%1,%2,%3}, {%4,%5,%6,%7}, {%8,%9}, {%0,%1,%2,%3};\n"
        : "+f"(c[0]), "+f"(c[1]), "+f"(c[2]), "+f"(c[3])
        : "r"(a[0]), "r"(a[1]), "r"(a[2]), "r"(a[3]), "r"(b[0]), "r"(b[1]));
}

template <int EPI>
__global__ __launch_bounds__(256, 2)
void gemm2(const __nv_bfloat16* __restrict__ Ah,
           const __nv_bfloat16* __restrict__ Al,
           const __nv_bfloat16* __restrict__ Wh,
           const __nv_bfloat16* __restrict__ Wl,
           const float* __restrict__ bias_or_dis,
           __nv_bfloat16* __restrict__ outgb,
           __nv_bfloat16* __restrict__ outh,
           __nv_bfloat16* __restrict__ outl) {
    extern __shared__ char sm[];
    const int tid = threadIdx.x;       // 256
    const int row0 = blockIdx.x * 64;

    // Copy A planes (64 rows) + W planes (128 rows) into ASTR-strided smem.
    {
        const uint4* sA0 = (const uint4*)(Ah + (size_t)row0 * 128);
        const uint4* sA1 = (const uint4*)(Al + (size_t)row0 * 128);
#pragma unroll
        for (int i = 0; i < 4; i++) {
            int idx = i * 256 + tid;   // 0..1023
            int row = idx >> 4;
            int q = idx & 15;
            *(uint4*)(sm + SM_AH + row * ASTR + q * 16) = sA0[idx];
            *(uint4*)(sm + SM_AL + row * ASTR + q * 16) = sA1[idx];
        }
        const uint4* sB0 = (const uint4*)Wh;
        const uint4* sB1 = (const uint4*)Wl;
#pragma unroll
        for (int i = 0; i < 8; i++) {
            int idx = i * 256 + tid;   // 0..2047
            int row = idx >> 4;
            int q = idx & 15;
            *(uint4*)(sm + SM_BH + row * ASTR + q * 16) = sB0[idx];
            *(uint4*)(sm + SM_BL + row * ASTR + q * 16) = sB1[idx];
        }
    }
    __syncthreads();

    const int w = tid >> 5;
    const int lane = tid & 31;
    const int gq = lane >> 2;
    const int tq = lane & 3;
    const int r0 = (w & 1) * 32;
    const int c0 = (w >> 1) * 32;

    float acc[2][4][4];
#pragma unroll
    for (int mi = 0; mi < 2; mi++)
#pragma unroll
        for (int ni = 0; ni < 4; ni++)
#pragma unroll
            for (int j = 0; j < 4; j++) acc[mi][ni][j] = 0.0f;

#pragma unroll
    for (int kb = 0; kb < 8; kb++) {
        const int k0 = kb * 16;
        uint32_t ah[2][4], al[2][4];
#pragma unroll
        for (int mi = 0; mi < 2; mi++) {
            int rr = r0 + mi * 16 + gq;
            const char* p0 = sm + rr * ASTR + (k0 + tq * 2) * 2;
            const char* p1 = sm + (rr + 8) * ASTR + (k0 + tq * 2) * 2;
            ah[mi][0] = *(const uint32_t*)(p0 + SM_AH);
            ah[mi][1] = *(const uint32_t*)(p1 + SM_AH);
            ah[mi][2] = *(const uint32_t*)(p0 + SM_AH + 16);
            ah[mi][3] = *(const uint32_t*)(p1 + SM_AH + 16);
            al[mi][0] = *(const uint32_t*)(p0 + SM_AL);
            al[mi][1] = *(const uint32_t*)(p1 + SM_AL);
            al[mi][2] = *(const uint32_t*)(p0 + SM_AL + 16);
            al[mi][3] = *(const uint32_t*)(p1 + SM_AL + 16);
        }
        uint32_t bh[4][2], bl[4][2];
#pragma unroll
        for (int ni = 0; ni < 4; ni++) {
            int nn = c0 + ni * 8 + gq;
            const char* pb = sm + nn * ASTR + (k0 + tq * 2) * 2;
            bh[ni][0] = *(const uint32_t*)(pb + SM_BH);
            bh[ni][1] = *(const uint32_t*)(pb + SM_BH + 16);
            bl[ni][0] = *(const uint32_t*)(pb + SM_BL);
            bl[ni][1] = *(const uint32_t*)(pb + SM_BL + 16);
        }
#pragma unroll
        for (int ni = 0; ni < 4; ni++) {
            mma_bf16(acc[0][ni], ah[0], bh[ni]);
            mma_bf16(acc[1][ni], ah[1], bh[ni]);
            mma_bf16(acc[0][ni], ah[0], bl[ni]);
            mma_bf16(acc[1][ni], ah[1], bl[ni]);
            mma_bf16(acc[0][ni], al[0], bh[ni]);
            mma_bf16(acc[1][ni], al[1], bh[ni]);
        }
    }

    // Epilogue
#pragma unroll
    for (int mi = 0; mi < 2; mi++) {
        int r = row0 + r0 + mi * 16 + gq;
        float s0 = 0.f, s1 = 0.f;
        if (EPI == 1) { s0 = bias_or_dis[r]; s1 = bias_or_dis[r + 8]; }
#pragma unroll
        for (int ni = 0; ni < 4; ni++) {
            int c = c0 + ni * 8 + tq * 2;
            if (EPI == 1) {
                ((uint32_t*)outgb)[((size_t)r * 128 + c) >> 1] =
                    pack_bf2(acc[mi][ni][0] * s0, acc[mi][ni][1] * s0);
                ((uint32_t*)outgb)[((size_t)(r + 8) * 128 + c) >> 1] =
                    pack_bf2(acc[mi][ni][2] * s1, acc[mi][ni][3] * s1);
            } else {
                float b0 = bias_or_dis[c], b1 = bias_or_dis[c + 1];
                uint32_t hi, lo;
                split2(acc[mi][ni][0] + b0, acc[mi][ni][1] + b1, hi, lo);
                ((uint32_t*)outh)[((size_t)r * 128 + c) >> 1] = hi;
                ((uint32_t*)outl)[((size_t)r * 128 + c) >> 1] = lo;
                split2(acc[mi][ni][2] + b0, acc[mi][ni][3] + b1, hi, lo);
                ((uint32_t*)outh)[((size_t)(r + 8) * 128 + c) >> 1] = hi;
                ((uint32_t*)outl)[((size_t)(r + 8) * 128 + c) >> 1] = lo;
            }
        }
    }
}

// ===========================================================================
// CSR gather v3: one warp per node; half-warp per edge (uint4 = 8 cols/lane).
// h[n] = relu(dis[n]*(sum g[col[e]] + g[n]) + b) -> bf16 hi/lo planes
// ===========================================================================
__global__ void gather_kernel(const float* __restrict__ b,
                              __nv_bfloat16* __restrict__ outh,
                              __nv_bfloat16* __restrict__ outl) {
    int w = (blockIdx.x * blockDim.x + threadIdx.x) >> 5;
    if (w >= NN) return;
    const int lane = threadIdx.x & 31;
    const int half = lane >> 4;
    const int li = lane & 15;
    int beg = g_rowptr[w];
    int end = g_rowptr[w + 1];

    const uint4* G4 = (const uint4*)g_gb;   // 16 uint4 per row
    float a[8] = {0, 0, 0, 0, 0, 0, 0, 0};
    float a2[8] = {0, 0, 0, 0, 0, 0, 0, 0};
    if (half == 0) acc8(a, G4[(size_t)w * 16 + li]);   // self term

    int e = beg;
    while (e < end) {
        int cnt = min(end - e, 32);
        int c = (lane < cnt) ? g_col[e + lane] : 0;
        int t = 0;
        for (; t + 8 <= cnt; t += 8) {
            int s0 = __shfl_sync(0xffffffffu, c, t + half);
            int s1 = __shfl_sync(0xffffffffu, c, t + 2 + half);
            int s2 = __shfl_sync(0xffffffffu, c, t + 4 + half);
            int s3 = __shfl_sync(0xffffffffu, c, t + 6 + half);
            uint4 v0 = G4[(size_t)s0 * 16 + li];
            uint4 v1 = G4[(size_t)s1 * 16 + li];
            uint4 v2 = G4[(size_t)s2 * 16 + li];
            uint4 v3 = G4[(size_t)s3 * 16 + li];
            acc8(a, v0);
            acc8(a2, v1);
            acc8(a, v2);
            acc8(a2, v3);
        }
        for (; t + 2 <= cnt; t += 2) {
            int s0 = __shfl_sync(0xffffffffu, c, t + half);
            uint4 v0 = G4[(size_t)s0 * 16 + li];
            acc8(a, v0);
        }
        if (t < cnt) {   // odd leftover: half 0 only
            int s0 = __shfl_sync(0xffffffffu, c, t);
            if (half == 0) {
                uint4 v0 = G4[(size_t)s0 * 16 + li];
                acc8(a2, v0);
            }
        }
        e += cnt;
    }
#pragma unroll
    for (int j = 0; j < 8; j++) a[j] += a2[j];
#pragma unroll
    for (int j = 0; j < 8; j++) a[j] += __shfl_down_sync(0xffffffffu, a[j], 16);

    if (half == 0) {
        float sc = g_dis[w];
        float4 b0 = *(const float4*)(b + li * 8);
        float4 b1 = *(const float4*)(b + li * 8 + 4);
        float o[8];
        o[0] = fmaxf(fmaf(sc, a[0], b0.x), 0.0f);
        o[1] = fmaxf(fmaf(sc, a[1], b0.y), 0.0f);
        o[2] = fmaxf(fmaf(sc, a[2], b0.z), 0.0f);
        o[3] = fmaxf(fmaf(sc, a[3], b0.w), 0.0f);
        o[4] = fmaxf(fmaf(sc, a[4], b1.x), 0.0f);
        o[5] = fmaxf(fmaf(sc, a[5], b1.y), 0.0f);
        o[6] = fmaxf(fmaf(sc, a[6], b1.z), 0.0f);
        o[7] = fmaxf(fmaf(sc, a[7], b1.w), 0.0f);
        uint32_t h0, l0, h1, l1, h2, l2, h3, l3;
        split2(o[0], o[1], h0, l0);
        split2(o[2], o[3], h1, l1);
        split2(o[4], o[5], h2, l2);
        split2(o[6], o[7], h3, l3);
        ((uint4*)outh)[(size_t)w * 16 + li] = make_uint4(h0, h1, h2, h3);
        ((uint4*)outl)[(size_t)w * 16 + li] = make_uint4(l0, l1, l2, l3);
    }
}

// ===========================================================================
// Pool (reads bf16 planes) + head
// ===========================================================================
__global__ void pool_kernel(const int* __restrict__ batch,
                            const __nv_bfloat16* __restrict__ ph,
                            const __nv_bfloat16* __restrict__ pl) {
    __shared__ float s[GG * HH];
    __shared__ float c[GG];
    int tid = threadIdx.x;  // 128
#pragma unroll
    for (int i = 0; i < GG; i++) s[i * HH + tid] = 0.0f;
    if (tid < GG) c[tid] = 0.0f;
    __syncthreads();

    for (int n = blockIdx.x; n < NN; n += gridDim.x) {
        int b = batch[n];
        float v = __bfloat162float(ph[(size_t)n * HH + tid]) +
                  __bfloat162float(pl[(size_t)n * HH + tid]);
        s[b * HH + tid] += v;
        if (tid == 0) c[b] += 1.0f;
    }
    __syncthreads();
#pragma unroll
    for (int i = 0; i < GG; i++) atomicAdd(&g_pool[i * HH + tid], s[i * HH + tid]);
    if (tid < GG) atomicAdd(&g_pool[GG * HH + tid], c[tid]);
}

__global__ void head_kernel(const float* __restrict__ Wf1,
                            const float* __restrict__ bf1,
                            const float* __restrict__ Wf2,
                            const float* __restrict__ bf2,
                            float* __restrict__ out) {
    __shared__ float P[GG * HH];
    __shared__ float Z[GG * 64];
    int tid = threadIdx.x;

    for (int i = tid; i < GG * HH; i += 1024) {
        float cnt = g_pool[GG * HH + i / HH];
        P[i] = g_pool[i] / fmaxf(cnt, 1.0f);
    }
    __syncthreads();

    {
        int g = tid >> 6;
        int j = tid & 63;
        float acc = bf1[j];
        const float* p = P + g * HH;
#pragma unroll 8
        for (int k = 0; k < HH; k++) acc += p[k] * Wf1[k * 64 + j];
        Z[g * 64 + j] = fmaxf(acc, 0.0f);
    }
    __syncthreads();

    if (tid < GG * CC) {
        int g = tid / CC;
        int c = tid % CC;
        float acc = bf2[c];
        const float* z = Z + g * 64;
#pragma unroll
        for (int j = 0; j < 64; j++) acc += z[j] * Wf2[j * CC + c];
        out[g * CC + c] = acc;
    }
}

// ===========================================================================
extern "C" void kernel_launch(void* const* d_in, const int* in_sizes, int n_in,
                              void* d_out, int out_size) {
    const float* x = (const float*)d_in[0];
    const int* edge = (const int*)d_in[1];     // int32
    const int* batch = (const int*)d_in[2];    // int32
    const float* W_in = (const float*)d_in[3];
    const float* b_in = (const float*)d_in[4];
    const float* W1 = (const float*)d_in[5];
    const float* b1 = (const float*)d_in[6];
    const float* W2 = (const float*)d_in[7];
    const float* b2 = (const float*)d_in[8];
    const float* Wf1 = (const float*)d_in[9];
    const float* bf1 = (const float*)d_in[10];
    const float* Wf2 = (const float*)d_in[11];
    const float* bf2 = (const float*)d_in[12];
    float* out = (float*)d_out;

    const int* src = edge;
    const int* dst = edge + EE;

    void *p_deg, *p_pool, *p_gb, *p_dis;
    void *p_pah, *p_pal, *p_pbh, *p_pbl, *p_wh, *p_wl;
    cudaGetSymbolAddress(&p_deg, g_deg);
    cudaGetSymbolAddress(&p_pool, g_pool);
    cudaGetSymbolAddress(&p_gb, g_gb);
    cudaGetSymbolAddress(&p_dis, g_dis);
    cudaGetSymbolAddress(&p_pah, g_pah);
    cudaGetSymbolAddress(&p_pal, g_pal);
    cudaGetSymbolAddress(&p_pbh, g_pbh);
    cudaGetSymbolAddress(&p_pbl, g_pbl);
    cudaGetSymbolAddress(&p_wh, g_wh);
    cudaGetSymbolAddress(&p_wl, g_wl);
    __nv_bfloat16* pah = (__nv_bfloat16*)p_pah;
    __nv_bfloat16* pal = (__nv_bfloat16*)p_pal;
    __nv_bfloat16* pbh = (__nv_bfloat16*)p_pbh;
    __nv_bfloat16* pbl = (__nv_bfloat16*)p_pbl;
    __nv_bfloat16* wh = (__nv_bfloat16*)p_wh;
    __nv_bfloat16* wl = (__nv_bfloat16*)p_wl;
    __nv_bfloat16* gb = (__nv_bfloat16*)p_gb;

    cudaFuncSetAttribute(gemm2<0>, cudaFuncAttributeMaxDynamicSharedMemorySize, SM_GEMM_TOTAL);
    cudaFuncSetAttribute(gemm2<1>, cudaFuncAttributeMaxDynamicSharedMemorySize, SM_GEMM_TOTAL);

    const int gemmGrid = NP / 64;  // 626

    // Launch order arranged so gemm0 is the 5th launch (profiled slot).
    cudaMemsetAsync(p_deg, 0, NN * sizeof(int));                 // 1
    conv_w_kernel<<<dim3(64, 3), 256>>>(W_in, W1, W2);           // 2
    conv_x_kernel<<<(NP * 32 + 255) / 256, 256>>>(x);            // 3
    deg_kernel<<<(EE / 4 + 255) / 256, 256>>>(dst);              // 4
    gemm2<0><<<gemmGrid, 256, SM_GEMM_TOTAL>>>(pah, pal, wh, wl, b_in,  // 5 <- profiled
                                               nullptr, pbh, pbl);
    scan1_kernel<<<40, 1024>>>();                                // 6
    scan2_kernel<<<1, 64>>>();                                   // 7
    scan3_kernel<<<40, 1024>>>();                                // 8
    fill_kernel<<<(EE / 4 + 255) / 256, 256>>>(src, dst);        // 9

    // Layer 1: g = (h0 @ W1)*dis (bf16); h1 = relu(dis*(gather+self)+b1) -> planes A
    gemm2<1><<<gemmGrid, 256, SM_GEMM_TOTAL>>>(pbh, pbl, wh + HH * HH, wl + HH * HH,
                                               (const float*)p_dis, gb, nullptr, nullptr);
    gather_kernel<<<(NN * 32 + 255) / 256, 256>>>(b1, pah, pal);

    // Layer 2: planes A -> g -> planes B
    gemm2<1><<<gemmGrid, 256, SM_GEMM_TOTAL>>>(pah, pal, wh + 2 * HH * HH, wl + 2 * HH * HH,
                                               (const float*)p_dis, gb, nullptr, nullptr);
    gather_kernel<<<(NN * 32 + 255) / 256, 256>>>(b2, pbh, pbl);

    // Pool + head
    cudaMemsetAsync(p_pool, 0, (GG * HH + GG) * sizeof(float));
    pool_kernel<<<256, 128>>>(batch, pbh, pbl);
    head_kernel<<<1, 1024>>>(Wf1, bf1, Wf2, bf2, out);
}

// round 12
// speedup vs baseline: 1.3234x; 1.3234x over previous
#include <cuda_runtime.h>
#include <cuda_bf16.h>
#include <cstdint>

#define NN 40000
#define NP 40064          // padded: 313 * 128
#define EE 640000
#define HH 128
#define GG 16
#define CC 10

// Scratch (static device globals). 16B aligned.
__device__ __align__(16) __nv_bfloat16 g_pah[NP * HH];  // plane-pair A (hi/lo)
__device__ __align__(16) __nv_bfloat16 g_pal[NP * HH];
__device__ __align__(16) __nv_bfloat16 g_pbh[NP * HH];  // plane-pair B
__device__ __align__(16) __nv_bfloat16 g_pbl[NP * HH];
__device__ __align__(16) __nv_bfloat16 g_gb[NP * HH];   // g = (h@W)*dis, bf16
__device__ __align__(16) float g_dis[NP];               // deg_inv_sqrt (pad stays 0)
__device__ __align__(16) __nv_bfloat16 g_wh[3 * HH * HH];  // W hi, transposed [n][k]
__device__ __align__(16) __nv_bfloat16 g_wl[3 * HH * HH];  // W lo
__device__ int   g_deg[NN];
__device__ int   g_rank[EE];
__device__ int   g_rowptr[NN + 1];
__device__ int   g_col[EE];
__device__ int   g_bsum[64];
__device__ int   g_boff[64];
__device__ __align__(16) float g_pool[GG * HH + GG];

// split two floats into packed bf16x2 hi and lo (lo = residual)
__device__ __forceinline__ void split2(float a, float b, uint32_t& hi, uint32_t& lo) {
    __nv_bfloat16 ah = __float2bfloat16(a);
    __nv_bfloat16 bh = __float2bfloat16(b);
    __nv_bfloat16 al = __float2bfloat16(a - __bfloat162float(ah));
    __nv_bfloat16 bl = __float2bfloat16(b - __bfloat162float(bh));
    hi = (uint32_t)__bfloat16_as_ushort(ah) | ((uint32_t)__bfloat16_as_ushort(bh) << 16);
    lo = (uint32_t)__bfloat16_as_ushort(al) | ((uint32_t)__bfloat16_as_ushort(bl) << 16);
}

__device__ __forceinline__ uint32_t pack_bf2(float a, float b) {
    __nv_bfloat162 t = __floats2bfloat162_rn(a, b);
    return *(uint32_t*)&t;
}

__device__ __forceinline__ float2 unpack_bf2(uint32_t u) {
    return __bfloat1622float2(*(__nv_bfloat162*)&u);
}

// ===========================================================================
// CSR build
// ===========================================================================
__global__ void deg_kernel(const int* __restrict__ dst) {
    int e0 = 4 * (blockIdx.x * blockDim.x + threadIdx.x);
#pragma unroll
    for (int j = 0; j < 4; j++) {
        int e = e0 + j;
        if (e < EE) g_rank[e] = atomicAdd(&g_deg[dst[e]], 1);
    }
}

__global__ void scan1_kernel() {
    __shared__ int s[1024];
    int t = threadIdx.x;
    int n = blockIdx.x * 1024 + t;
    int d = (n < NN) ? g_deg[n] : 0;
    s[t] = d;
    __syncthreads();
    for (int off = 1; off < 1024; off <<= 1) {
        int v = (t >= off) ? s[t - off] : 0;
        __syncthreads();
        s[t] += v;
        __syncthreads();
    }
    if (n < NN) g_rowptr[n] = s[t] - d;   // local exclusive
    if (t == 1023) g_bsum[blockIdx.x] = s[t];
}

__global__ void scan2_kernel() {
    __shared__ int s[64];
    int t = threadIdx.x;  // 64
    int v = (t < 40) ? g_bsum[t] : 0;
    s[t] = v;
    __syncthreads();
    for (int off = 1; off < 64; off <<= 1) {
        int u = (t >= off) ? s[t - off] : 0;
        __syncthreads();
        s[t] += u;
        __syncthreads();
    }
    if (t < 40) g_boff[t] = s[t] - v;
}

__global__ void scan3_kernel() {
    int n = blockIdx.x * 1024 + threadIdx.x;
    if (n >= NN) {
        if (n == NN) g_rowptr[NN] = EE;
        return;
    }
    int r = g_rowptr[n] + g_boff[blockIdx.x];
    g_rowptr[n] = r;
    g_dis[n] = rsqrtf((float)g_deg[n] + 1.0f);
}

// Atomic-free fill: pos = rowptr[dst] + rank (rank recorded during deg).
__global__ void fill_kernel(const int* __restrict__ src,
                            const int* __restrict__ dst) {
    int e0 = 4 * (blockIdx.x * blockDim.x + threadIdx.x);
#pragma unroll
    for (int j = 0; j < 4; j++) {
        int e = e0 + j;
        if (e < EE) g_col[g_rowptr[dst[e]] + g_rank[e]] = src[e];
    }
}

// ===========================================================================
// Conversion kernels
// ===========================================================================
__global__ void conv_x_kernel(const float* __restrict__ x) {
    int idx = blockIdx.x * blockDim.x + threadIdx.x;  // 0 .. NP*32-1
    if (idx >= NP * 32) return;
    int row = idx >> 5;
    int q = idx & 31;
    float4 v = (row < NN) ? ((const float4*)x)[(size_t)row * 32 + q]
                          : make_float4(0.f, 0.f, 0.f, 0.f);
    uint32_t h0, l0, h1, l1;
    split2(v.x, v.y, h0, l0);
    split2(v.z, v.w, h1, l1);
    ((uint2*)g_pah)[idx] = make_uint2(h0, h1);
    ((uint2*)g_pal)[idx] = make_uint2(l0, l1);
}

__global__ void conv_w_kernel(const float* __restrict__ W0,
                              const float* __restrict__ W1,
                              const float* __restrict__ W2) {
    const float* W = (blockIdx.y == 0) ? W0 : (blockIdx.y == 1) ? W1 : W2;
    __nv_bfloat16* Wh = g_wh + blockIdx.y * HH * HH;
    __nv_bfloat16* Wl = g_wl + blockIdx.y * HH * HH;
    int idx = blockIdx.x * 256 + threadIdx.x;  // 0..16383
    int k = idx >> 7;
    int n = idx & 127;
    float v = W[k * 128 + n];
    __nv_bfloat16 hi = __float2bfloat16(v);
    __nv_bfloat16 lo = __float2bfloat16(v - __bfloat162float(hi));
    Wh[n * 128 + k] = hi;
    Wl[n * 128 + k] = lo;
}

// ===========================================================================
// HMMA pieces (validated R8/R10 fragment layout). 256 thr, warp tile 32x64.
// ===========================================================================
#define ASTR 272
#define PL (128 * ASTR)    // one plane: 34816 bytes

__device__ __forceinline__ void mma_bf16(float* c, const uint32_t* a, const uint32_t* b) {
    asm volatile(
        "mma.sync.aligned.m16n8k16.row.col.f32.bf16.bf16.f32 "
        "{%0,%1,%2,%3}, {%4,%5,%6,%7}, {%8,%9}, {%0,%1,%2,%3};\n"
        : "+f"(c[0]), "+f"(c[1]), "+f"(c[2]), "+f"(c[3])
        : "r"(a[0]), "r"(a[1]), "r"(a[2]), "r"(a[3]), "r"(b[0]), "r"(b[1]));
}

// Mainloop: A planes at sm+aOff(hi)/aOff+PL(lo), B planes at sm+bOff/bOff+PL.
// acc[2][8][4] for warp tile (r0 = (w&3)*32, c0 = (w>>2)*64).
__device__ __forceinline__ void mma_mainloop(const char* sm, int aOff, int bOff,
                                             int r0, int c0, int gq, int tq,
                                             float acc[2][8][4]) {
#pragma unroll
    for (int kb = 0; kb < 8; kb++) {
        const int k0 = kb * 16;
        uint32_t ah[2][4], al[2][4];
#pragma unroll
        for (int mi = 0; mi < 2; mi++) {
            int rr = r0 + mi * 16 + gq;
            const char* p0 = sm + aOff + rr * ASTR + (k0 + tq * 2) * 2;
            const char* p1 = sm + aOff + (rr + 8) * ASTR + (k0 + tq * 2) * 2;
            ah[mi][0] = *(const uint32_t*)(p0);
            ah[mi][1] = *(const uint32_t*)(p1);
            ah[mi][2] = *(const uint32_t*)(p0 + 16);
            ah[mi][3] = *(const uint32_t*)(p1 + 16);
            al[mi][0] = *(const uint32_t*)(p0 + PL);
            al[mi][1] = *(const uint32_t*)(p1 + PL);
            al[mi][2] = *(const uint32_t*)(p0 + PL + 16);
            al[mi][3] = *(const uint32_t*)(p1 + PL + 16);
        }
        uint32_t bh[8][2], bl[8][2];
#pragma unroll
        for (int ni = 0; ni < 8; ni++) {
            int nn = c0 + ni * 8 + gq;
            const char* pb = sm + bOff + nn * ASTR + (k0 + tq * 2) * 2;
            bh[ni][0] = *(const uint32_t*)(pb);
            bh[ni][1] = *(const uint32_t*)(pb + 16);
            bl[ni][0] = *(const uint32_t*)(pb + PL);
            bl[ni][1] = *(const uint32_t*)(pb + PL + 16);
        }
#pragma unroll
        for (int ni = 0; ni < 8; ni++) {
            mma_bf16(acc[0][ni], ah[0], bh[ni]);
            mma_bf16(acc[1][ni], ah[1], bh[ni]);
            mma_bf16(acc[0][ni], ah[0], bl[ni]);
            mma_bf16(acc[1][ni], ah[1], bl[ni]);
            mma_bf16(acc[0][ni], al[0], bh[ni]);
            mma_bf16(acc[1][ni], al[1], bh[ni]);
        }
    }
}

// Copy a 128-row bf16 plane pair (global, contiguous) into ASTR-strided smem.
__device__ __forceinline__ void copy_planes(char* sm, int off,
                                            const __nv_bfloat16* hi,
                                            const __nv_bfloat16* lo, int tid) {
    const uint4* s0 = (const uint4*)hi;
    const uint4* s1 = (const uint4*)lo;
#pragma unroll
    for (int i = 0; i < 8; i++) {
        int idx = i * 256 + tid;   // 0..2047
        int row = idx >> 4;
        int q = idx & 15;
        *(uint4*)(sm + off + row * ASTR + q * 16) = s0[idx];
        *(uint4*)(sm + off + PL + row * ASTR + q * 16) = s1[idx];
    }
}

// ===========================================================================
// Fused GEMM0+GEMM1: g1 = ((x@W_in + b_in) @ W1) * dis  -> bf16 g_gb
// smem: A planes (x tile / reused for T), B0 = W_in, B1 = W1. 6 planes = 204KB.
// ===========================================================================
#define SMF_A  0
#define SMF_B0 (2 * PL)
#define SMF_B1 (4 * PL)
#define SMF_TOTAL (6 * PL)   // 208896

__global__ __launch_bounds__(256, 1)
void gemm01_kernel(const float* __restrict__ bias,
                   const float* __restrict__ dis,
                   __nv_bfloat16* __restrict__ outgb) {
    extern __shared__ char sm[];
    const int tid = threadIdx.x;
    const int row0 = blockIdx.x * 128;

    copy_planes(sm, SMF_A, g_pah + (size_t)row0 * 128, g_pal + (size_t)row0 * 128, tid);
    copy_planes(sm, SMF_B0, g_wh, g_wl, tid);
    copy_planes(sm, SMF_B1, g_wh + HH * HH, g_wl + HH * HH, tid);
    __syncthreads();

    const int w = tid >> 5;
    const int lane = tid & 31;
    const int gq = lane >> 2;
    const int tq = lane & 3;
    const int r0 = (w & 3) * 32;
    const int c0 = (w >> 2) * 64;

    float acc[2][8][4];
#pragma unroll
    for (int mi = 0; mi < 2; mi++)
#pragma unroll
        for (int ni = 0; ni < 8; ni++)
#pragma unroll
            for (int j = 0; j < 4; j++) acc[mi][ni][j] = 0.0f;

    mma_mainloop(sm, SMF_A, SMF_B0, r0, c0, gq, tq, acc);
    __syncthreads();   // all warps done reading A planes

    // T = acc + bias -> split into A planes (overwrite), layout [row][col]
#pragma unroll
    for (int mi = 0; mi < 2; mi++) {
        int rr = r0 + mi * 16 + gq;
#pragma unroll
        for (int ni = 0; ni < 8; ni++) {
            int c = c0 + ni * 8 + tq * 2;
            float b0 = bias[c], b1 = bias[c + 1];
            uint32_t hi, lo;
            split2(acc[mi][ni][0] + b0, acc[mi][ni][1] + b1, hi, lo);
            *(uint32_t*)(sm + SMF_A + rr * ASTR + c * 2) = hi;
            *(uint32_t*)(sm + SMF_A + PL + rr * ASTR + c * 2) = lo;
            split2(acc[mi][ni][2] + b0, acc[mi][ni][3] + b1, hi, lo);
            *(uint32_t*)(sm + SMF_A + (rr + 8) * ASTR + c * 2) = hi;
            *(uint32_t*)(sm + SMF_A + PL + (rr + 8) * ASTR + c * 2) = lo;
        }
    }
    __syncthreads();

#pragma unroll
    for (int mi = 0; mi < 2; mi++)
#pragma unroll
        for (int ni = 0; ni < 8; ni++)
#pragma unroll
            for (int j = 0; j < 4; j++) acc[mi][ni][j] = 0.0f;

    mma_mainloop(sm, SMF_A, SMF_B1, r0, c0, gq, tq, acc);

    // Epilogue: *dis[row] -> bf16 g
#pragma unroll
    for (int mi = 0; mi < 2; mi++) {
        int r = row0 + r0 + mi * 16 + gq;
        float s0 = dis[r], s1 = dis[r + 8];
#pragma unroll
        for (int ni = 0; ni < 8; ni++) {
            int c = c0 + ni * 8 + tq * 2;
            ((uint32_t*)outgb)[((size_t)r * 128 + c) >> 1] =
                pack_bf2(acc[mi][ni][0] * s0, acc[mi][ni][1] * s0);
            ((uint32_t*)outgb)[((size_t)(r + 8) * 128 + c) >> 1] =
                pack_bf2(acc[mi][ni][2] * s1, acc[mi][ni][3] * s1);
        }
    }
}

// ===========================================================================
// Single GEMM (layer 2): g2 = (h1 @ W2) * dis -> bf16 g_gb. 4 planes = 136KB.
// ===========================================================================
#define SMG_A 0
#define SMG_B (2 * PL)
#define SMG_TOTAL (4 * PL)   // 139264

__global__ __launch_bounds__(256, 1)
void gemm_g_kernel(const __nv_bfloat16* __restrict__ Ah,
                   const __nv_bfloat16* __restrict__ Al,
                   const __nv_bfloat16* __restrict__ Wh,
                   const __nv_bfloat16* __restrict__ Wl,
                   const float* __restrict__ dis,
                   __nv_bfloat16* __restrict__ outgb) {
    extern __shared__ char sm[];
    const int tid = threadIdx.x;
    const int row0 = blockIdx.x * 128;

    copy_planes(sm, SMG_A, Ah + (size_t)row0 * 128, Al + (size_t)row0 * 128, tid);
    copy_planes(sm, SMG_B, Wh, Wl, tid);
    __syncthreads();

    const int w = tid >> 5;
    const int lane = tid & 31;
    const int gq = lane >> 2;
    const int tq = lane & 3;
    const int r0 = (w & 3) * 32;
    const int c0 = (w >> 2) * 64;

    float acc[2][8][4];
#pragma unroll
    for (int mi = 0; mi < 2; mi++)
#pragma unroll
        for (int ni = 0; ni < 8; ni++)
#pragma unroll
            for (int j = 0; j < 4; j++) acc[mi][ni][j] = 0.0f;

    mma_mainloop(sm, SMG_A, SMG_B, r0, c0, gq, tq, acc);

#pragma unroll
    for (int mi = 0; mi < 2; mi++) {
        int r = row0 + r0 + mi * 16 + gq;
        float s0 = dis[r], s1 = dis[r + 8];
#pragma unroll
        for (int ni = 0; ni < 8; ni++) {
            int c = c0 + ni * 8 + tq * 2;
            ((uint32_t*)outgb)[((size_t)r * 128 + c) >> 1] =
                pack_bf2(acc[mi][ni][0] * s0, acc[mi][ni][1] * s0);
            ((uint32_t*)outgb)[((size_t)(r + 8) * 128 + c) >> 1] =
                pack_bf2(acc[mi][ni][2] * s1, acc[mi][ni][3] * s1);
        }
    }
}

// ===========================================================================
// CSR gather (bf16 g) + fused finalize: one warp per node, f32 accumulate.
// h[n] = relu(dis[n] * (sum g[col[e]] + g[n]) + b)  -> bf16 hi/lo planes
// ===========================================================================
__global__ void gather_kernel(const float* __restrict__ b,
                              __nv_bfloat16* __restrict__ outh,
                              __nv_bfloat16* __restrict__ outl) {
    int w = (blockIdx.x * blockDim.x + threadIdx.x) >> 5;
    if (w >= NN) return;
    int lane = threadIdx.x & 31;
    int beg = g_rowptr[w];
    int end = g_rowptr[w + 1];

    const uint2* G = (const uint2*)g_gb;
    float4 a0, a1 = make_float4(0.f, 0.f, 0.f, 0.f);
    {
        uint2 sv = G[(size_t)w * 32 + lane];   // self term
        float2 f0 = unpack_bf2(sv.x), f1 = unpack_bf2(sv.y);
        a0 = make_float4(f0.x, f0.y, f1.x, f1.y);
    }

    int e = beg;
    while (e < end) {
        int cnt = min(end - e, 32);
        int c = (lane < cnt) ? g_col[e + lane] : 0;
        int i = 0;
        for (; i + 8 <= cnt; i += 8) {
            int s0 = __shfl_sync(0xffffffffu, c, i);
            int s1 = __shfl_sync(0xffffffffu, c, i + 1);
            int s2 = __shfl_sync(0xffffffffu, c, i + 2);
            int s3 = __shfl_sync(0xffffffffu, c, i + 3);
            int s4 = __shfl_sync(0xffffffffu, c, i + 4);
            int s5 = __shfl_sync(0xffffffffu, c, i + 5);
            int s6 = __shfl_sync(0xffffffffu, c, i + 6);
            int s7 = __shfl_sync(0xffffffffu, c, i + 7);
            uint2 v0 = G[(size_t)s0 * 32 + lane];
            uint2 v1 = G[(size_t)s1 * 32 + lane];
            uint2 v2 = G[(size_t)s2 * 32 + lane];
            uint2 v3 = G[(size_t)s3 * 32 + lane];
            uint2 v4 = G[(size_t)s4 * 32 + lane];
            uint2 v5 = G[(size_t)s5 * 32 + lane];
            uint2 v6 = G[(size_t)s6 * 32 + lane];
            uint2 v7 = G[(size_t)s7 * 32 + lane];
            float2 f;
            f = unpack_bf2(v0.x); a0.x += f.x; a0.y += f.y;
            f = unpack_bf2(v0.y); a0.z += f.x; a0.w += f.y;
            f = unpack_bf2(v1.x); a1.x += f.x; a1.y += f.y;
            f = unpack_bf2(v1.y); a1.z += f.x; a1.w += f.y;
            f = unpack_bf2(v2.x); a0.x += f.x; a0.y += f.y;
            f = unpack_bf2(v2.y); a0.z += f.x; a0.w += f.y;
            f = unpack_bf2(v3.x); a1.x += f.x; a1.y += f.y;
            f = unpack_bf2(v3.y); a1.z += f.x; a1.w += f.y;
            f = unpack_bf2(v4.x); a0.x += f.x; a0.y += f.y;
            f = unpack_bf2(v4.y); a0.z += f.x; a0.w += f.y;
            f = unpack_bf2(v5.x); a1.x += f.x; a1.y += f.y;
            f = unpack_bf2(v5.y); a1.z += f.x; a1.w += f.y;
            f = unpack_bf2(v6.x); a0.x += f.x; a0.y += f.y;
            f = unpack_bf2(v6.y); a0.z += f.x; a0.w += f.y;
            f = unpack_bf2(v7.x); a1.x += f.x; a1.y += f.y;
            f = unpack_bf2(v7.y); a1.z += f.x; a1.w += f.y;
        }
        for (; i + 4 <= cnt; i += 4) {
            int s0 = __shfl_sync(0xffffffffu, c, i);
            int s1 = __shfl_sync(0xffffffffu, c, i + 1);
            int s2 = __shfl_sync(0xffffffffu, c, i + 2);
            int s3 = __shfl_sync(0xffffffffu, c, i + 3);
            uint2 v0 = G[(size_t)s0 * 32 + lane];
            uint2 v1 = G[(size_t)s1 * 32 + lane];
            uint2 v2 = G[(size_t)s2 * 32 + lane];
            uint2 v3 = G[(size_t)s3 * 32 + lane];
            float2 f;
            f = unpack_bf2(v0.x); a0.x += f.x; a0.y += f.y;
            f = unpack_bf2(v0.y); a0.z += f.x; a0.w += f.y;
            f = unpack_bf2(v1.x); a1.x += f.x; a1.y += f.y;
            f = unpack_bf2(v1.y); a1.z += f.x; a1.w += f.y;
            f = unpack_bf2(v2.x); a0.x += f.x; a0.y += f.y;
            f = unpack_bf2(v2.y); a0.z += f.x; a0.w += f.y;
            f = unpack_bf2(v3.x); a1.x += f.x; a1.y += f.y;
            f = unpack_bf2(v3.y); a1.z += f.x; a1.w += f.y;
        }
        for (; i < cnt; i++) {
            int s0 = __shfl_sync(0xffffffffu, c, i);
            uint2 v0 = G[(size_t)s0 * 32 + lane];
            float2 f;
            f = unpack_bf2(v0.x); a0.x += f.x; a0.y += f.y;
            f = unpack_bf2(v0.y); a0.z += f.x; a0.w += f.y;
        }
        e += cnt;
    }
    a0.x += a1.x; a0.y += a1.y; a0.z += a1.z; a0.w += a1.w;

    float sc = g_dis[w];
    float4 bb = *(const float4*)(b + lane * 4);
    float4 o;
    o.x = fmaxf(fmaf(sc, a0.x, bb.x), 0.0f);
    o.y = fmaxf(fmaf(sc, a0.y, bb.y), 0.0f);
    o.z = fmaxf(fmaf(sc, a0.z, bb.z), 0.0f);
    o.w = fmaxf(fmaf(sc, a0.w, bb.w), 0.0f);

    uint32_t h0, l0, h1, l1;
    split2(o.x, o.y, h0, l0);
    split2(o.z, o.w, h1, l1);
    ((uint2*)outh)[(size_t)w * 32 + lane] = make_uint2(h0, h1);
    ((uint2*)outl)[(size_t)w * 32 + lane] = make_uint2(l0, l1);
}

// ===========================================================================
// Pool (reads bf16 planes) + head
// ===========================================================================
__global__ void pool_kernel(const int* __restrict__ batch,
                            const __nv_bfloat16* __restrict__ ph,
                            const __nv_bfloat16* __restrict__ pl) {
    __shared__ float s[GG * HH];
    __shared__ float c[GG];
    int tid = threadIdx.x;  // 128
#pragma unroll
    for (int i = 0; i < GG; i++) s[i * HH + tid] = 0.0f;
    if (tid < GG) c[tid] = 0.0f;
    __syncthreads();

    for (int n = blockIdx.x; n < NN; n += gridDim.x) {
        int b = batch[n];
        float v = __bfloat162float(ph[(size_t)n * HH + tid]) +
                  __bfloat162float(pl[(size_t)n * HH + tid]);
        s[b * HH + tid] += v;
        if (tid == 0) c[b] += 1.0f;
    }
    __syncthreads();
#pragma unroll
    for (int i = 0; i < GG; i++) atomicAdd(&g_pool[i * HH + tid], s[i * HH + tid]);
    if (tid < GG) atomicAdd(&g_pool[GG * HH + tid], c[tid]);
}

__global__ void head_kernel(const float* __restrict__ Wf1,
                            const float* __restrict__ bf1,
                            const float* __restrict__ Wf2,
                            const float* __restrict__ bf2,
                            float* __restrict__ out) {
    __shared__ float P[GG * HH];
    __shared__ float Z[GG * 64];
    int tid = threadIdx.x;

    for (int i = tid; i < GG * HH; i += 1024) {
        float cnt = g_pool[GG * HH + i / HH];
        P[i] = g_pool[i] / fmaxf(cnt, 1.0f);
    }
    __syncthreads();

    {
        int g = tid >> 6;
        int j = tid & 63;
        float acc = bf1[j];
        const float* p = P + g * HH;
#pragma unroll 8
        for (int k = 0; k < HH; k++) acc += p[k] * Wf1[k * 64 + j];
        Z[g * 64 + j] = fmaxf(acc, 0.0f);
    }
    __syncthreads();

    if (tid < GG * CC) {
        int g = tid / CC;
        int c = tid % CC;
        float acc = bf2[c];
        const float* z = Z + g * 64;
#pragma unroll
        for (int j = 0; j < 64; j++) acc += z[j] * Wf2[j * CC + c];
        out[g * CC + c] = acc;
    }
}

// ===========================================================================
extern "C" void kernel_launch(void* const* d_in, const int* in_sizes, int n_in,
                              void* d_out, int out_size) {
    const float* x = (const float*)d_in[0];
    const int* edge = (const int*)d_in[1];     // int32
    const int* batch = (const int*)d_in[2];    // int32
    const float* W_in = (const float*)d_in[3];
    const float* b_in = (const float*)d_in[4];
    const float* W1 = (const float*)d_in[5];
    const float* b1 = (const float*)d_in[6];
    const float* W2 = (const float*)d_in[7];
    const float* b2 = (const float*)d_in[8];
    const float* Wf1 = (const float*)d_in[9];
    const float* bf1 = (const float*)d_in[10];
    const float* Wf2 = (const float*)d_in[11];
    const float* bf2 = (const float*)d_in[12];
    float* out = (float*)d_out;

    const int* src = edge;
    const int* dst = edge + EE;

    void *p_deg, *p_pool, *p_gb, *p_dis, *p_pah, *p_pal, *p_pbh, *p_pbl, *p_wh, *p_wl;
    cudaGetSymbolAddress(&p_deg, g_deg);
    cudaGetSymbolAddress(&p_pool, g_pool);
    cudaGetSymbolAddress(&p_gb, g_gb);
    cudaGetSymbolAddress(&p_dis, g_dis);
    cudaGetSymbolAddress(&p_pah, g_pah);
    cudaGetSymbolAddress(&p_pal, g_pal);
    cudaGetSymbolAddress(&p_pbh, g_pbh);
    cudaGetSymbolAddress(&p_pbl, g_pbl);
    cudaGetSymbolAddress(&p_wh, g_wh);
    cudaGetSymbolAddress(&p_wl, g_wl);
    __nv_bfloat16* pah = (__nv_bfloat16*)p_pah;
    __nv_bfloat16* pal = (__nv_bfloat16*)p_pal;
    __nv_bfloat16* pbh = (__nv_bfloat16*)p_pbh;
    __nv_bfloat16* pbl = (__nv_bfloat16*)p_pbl;
    __nv_bfloat16* wh = (__nv_bfloat16*)p_wh;
    __nv_bfloat16* wl = (__nv_bfloat16*)p_wl;
    __nv_bfloat16* gb = (__nv_bfloat16*)p_gb;

    cudaFuncSetAttribute(gemm01_kernel, cudaFuncAttributeMaxDynamicSharedMemorySize, SMF_TOTAL);
    cudaFuncSetAttribute(gemm_g_kernel, cudaFuncAttributeMaxDynamicSharedMemorySize, SMG_TOTAL);

    const int gemmGrid = NP / 128;  // 313

    // CSR build + dis
    cudaMemsetAsync(p_deg, 0, NN * sizeof(int));
    deg_kernel<<<(EE / 4 + 255) / 256, 256>>>(dst);
    scan1_kernel<<<40, 1024>>>();
    scan2_kernel<<<1, 64>>>();
    scan3_kernel<<<40, 1024>>>();
    fill_kernel<<<(EE / 4 + 255) / 256, 256>>>(src, dst);

    // Conversions
    conv_w_kernel<<<dim3(64, 3), 256>>>(W_in, W1, W2);
    conv_x_kernel<<<(NP * 32 + 255) / 256, 256>>>(x);

    // Fused layer0+1 GEMM: g1 = ((x@W_in + b_in) @ W1) * dis
    gemm01_kernel<<<gemmGrid, 256, SMF_TOTAL>>>(b_in, (const float*)p_dis, gb);
    gather_kernel<<<(NN * 32 + 255) / 256, 256>>>(b1, pah, pal);

    // Layer 2: g2 = (h1 @ W2) * dis ; h2 -> planes B
    gemm_g_kernel<<<gemmGrid, 256, SMG_TOTAL>>>(pah, pal, wh + 2 * HH * HH, wl + 2 * HH * HH,
                                                (const float*)p_dis, gb);
    gather_kernel<<<(NN * 32 + 255) / 256, 256>>>(b2, pbh, pbl);

    // Pool + head
    cudaMemsetAsync(p_pool, 0, (GG * HH + GG) * sizeof(float));
    pool_kernel<<<256, 128>>>(batch, pbh, pbl);
    head_kernel<<<1, 1024>>>(Wf1, bf1, Wf2, bf2, out);
}

// round 16
// speedup vs baseline: 1.8187x; 1.3742x over previous
#include <cuda_runtime.h>
#include <cuda_bf16.h>
#include <cstdint>

#define NN 40000
#define NP 40064          // padded: 313 * 128
#define EE 640000
#define HH 128
#define GG 16
#define CC 10

// Scratch (static device globals). 16B aligned.
__device__ __align__(16) __nv_bfloat16 g_pah[NP * HH];  // plane-pair A (hi/lo)
__device__ __align__(16) __nv_bfloat16 g_pal[NP * HH];
__device__ __align__(16) __nv_bfloat16 g_gb[NP * HH];   // g = (h@W)*dis, bf16
__device__ __align__(16) float g_dis[NP];               // deg_inv_sqrt (pad stays 0)
__device__ __align__(16) __nv_bfloat16 g_wh[3 * HH * HH];  // W hi, transposed [n][k]
__device__ __align__(16) __nv_bfloat16 g_wl[3 * HH * HH];  // W lo
__device__ int   g_deg[NN];
__device__ int   g_rank[EE];
__device__ int   g_rowptr[NN + 1];
__device__ int   g_col[EE];
__device__ int   g_bsum[64];
__device__ __align__(16) float g_pool[GG * HH + GG];

// split two floats into packed bf16x2 hi and lo (lo = residual)
__device__ __forceinline__ void split2(float a, float b, uint32_t& hi, uint32_t& lo) {
    __nv_bfloat16 ah = __float2bfloat16(a);
    __nv_bfloat16 bh = __float2bfloat16(b);
    __nv_bfloat16 al = __float2bfloat16(a - __bfloat162float(ah));
    __nv_bfloat16 bl = __float2bfloat16(b - __bfloat162float(bh));
    hi = (uint32_t)__bfloat16_as_ushort(ah) | ((uint32_t)__bfloat16_as_ushort(bh) << 16);
    lo = (uint32_t)__bfloat16_as_ushort(al) | ((uint32_t)__bfloat16_as_ushort(bl) << 16);
}

__device__ __forceinline__ uint32_t pack_bf2(float a, float b) {
    __nv_bfloat162 t = __floats2bfloat162_rn(a, b);
    return *(uint32_t*)&t;
}

__device__ __forceinline__ float2 unpack_bf2(uint32_t u) {
    return __bfloat1622float2(*(__nv_bfloat162*)&u);
}

// ===========================================================================
// CSR build
// ===========================================================================
__global__ void deg_kernel(const int* __restrict__ dst) {
    int e0 = 4 * (blockIdx.x * blockDim.x + threadIdx.x);
#pragma unroll
    for (int j = 0; j < 4; j++) {
        int e = e0 + j;
        if (e < EE) g_rank[e] = atomicAdd(&g_deg[dst[e]], 1);
    }
}

__global__ void dis_kernel() {
    int n = blockIdx.x * blockDim.x + threadIdx.x;
    if (n < NN) g_dis[n] = rsqrtf((float)g_deg[n] + 1.0f);
}

__global__ void scan1_kernel() {
    __shared__ int s[1024];
    int t = threadIdx.x;
    int n = blockIdx.x * 1024 + t;
    int d = (n < NN) ? g_deg[n] : 0;
    s[t] = d;
    __syncthreads();
    for (int off = 1; off < 1024; off <<= 1) {
        int v = (t >= off) ? s[t - off] : 0;
        __syncthreads();
        s[t] += v;
        __syncthreads();
    }
    if (n < NN) g_rowptr[n] = s[t] - d;   // local exclusive
    if (t == 1023) g_bsum[blockIdx.x] = s[t];
}

// scan3 with inlined block-offset reduction (replaces scan2).
__global__ void scan3_kernel() {
    __shared__ int blockoff;
    int t = threadIdx.x;
    if (t < 32) {
        int bid = (int)blockIdx.x;            // 0..39
        int v = (t < bid && t < 40) ? g_bsum[t] : 0;
        int t2 = t + 32;
        if (t2 < bid && t2 < 40) v += g_bsum[t2];
#pragma unroll
        for (int o = 16; o; o >>= 1) v += __shfl_down_sync(0xffffffffu, v, o);
        if (t == 0) blockoff = v;
    }
    __syncthreads();
    int n = blockIdx.x * 1024 + t;
    if (n < NN) g_rowptr[n] = g_rowptr[n] + blockoff;
    if (n == NN) g_rowptr[NN] = EE;
}

// Atomic-free fill: pos = rowptr[dst] + rank (rank recorded during deg).
__global__ void fill_kernel(const int* __restrict__ src,
                            const int* __restrict__ dst) {
    int e0 = 4 * (blockIdx.x * blockDim.x + threadIdx.x);
#pragma unroll
    for (int j = 0; j < 4; j++) {
        int e = e0 + j;
        if (e < EE) g_col[g_rowptr[dst[e]] + g_rank[e]] = src[e];
    }
}

// ===========================================================================
// Fused conversion: blocks [0,5008) split x -> planes A; [5008,5200) split W.
// ===========================================================================
#define XBLKS (NP * 32 / 256)   // 5008

__global__ void conv_xw_kernel(const float* __restrict__ x,
                               const float* __restrict__ W0,
                               const float* __restrict__ W1,
                               const float* __restrict__ W2) {
    int bid = blockIdx.x;
    if (bid < XBLKS) {
        int idx = bid * 256 + threadIdx.x;  // 0 .. NP*32-1
        int row = idx >> 5;
        int q = idx & 31;
        float4 v = (row < NN) ? ((const float4*)x)[(size_t)row * 32 + q]
                              : make_float4(0.f, 0.f, 0.f, 0.f);
        uint32_t h0, l0, h1, l1;
        split2(v.x, v.y, h0, l0);
        split2(v.z, v.w, h1, l1);
        ((uint2*)g_pah)[idx] = make_uint2(h0, h1);
        ((uint2*)g_pal)[idx] = make_uint2(l0, l1);
    } else {
        int b2 = bid - XBLKS;               // 0..191
        int wi = b2 >> 6;                   // matrix 0..2
        int blk = b2 & 63;
        const float* W = (wi == 0) ? W0 : (wi == 1) ? W1 : W2;
        __nv_bfloat16* Wh = g_wh + wi * HH * HH;
        __nv_bfloat16* Wl = g_wl + wi * HH * HH;
        int idx = blk * 256 + threadIdx.x;  // 0..16383
        int k = idx >> 7;
        int n = idx & 127;
        float v = W[k * 128 + n];
        __nv_bfloat16 hi = __float2bfloat16(v);
        __nv_bfloat16 lo = __float2bfloat16(v - __bfloat162float(hi));
        Wh[n * 128 + k] = hi;
        Wl[n * 128 + k] = lo;
    }
}

// ===========================================================================
// HMMA pieces (validated fragment layout). 256 thr, warp tile 32x64.
// ===========================================================================
#define ASTR 272
#define PL (128 * ASTR)    // one plane: 34816 bytes

__device__ __forceinline__ void mma_bf16(float* c, const uint32_t* a, const uint32_t* b) {
    asm volatile(
        "mma.sync.aligned.m16n8k16.row.col.f32.bf16.bf16.f32 "
        "{%0,%1,%2,%3}, {%4,%5,%6,%7}, {%8,%9}, {%0,%1,%2,%3};\n"
        : "+f"(c[0]), "+f"(c[1]), "+f"(c[2]), "+f"(c[3])
        : "r"(a[0]), "r"(a[1]), "r"(a[2]), "r"(a[3]), "r"(b[0]), "r"(b[1]));
}

__device__ __forceinline__ void mma_mainloop(const char* sm, int aOff, int bOff,
                                             int r0, int c0, int gq, int tq,
                                             float acc[2][8][4]) {
#pragma unroll
    for (int kb = 0; kb < 8; kb++) {
        const int k0 = kb * 16;
        uint32_t ah[2][4], al[2][4];
#pragma unroll
        for (int mi = 0; mi < 2; mi++) {
            int rr = r0 + mi * 16 + gq;
            const char* p0 = sm + aOff + rr * ASTR + (k0 + tq * 2) * 2;
            const char* p1 = sm + aOff + (rr + 8) * ASTR + (k0 + tq * 2) * 2;
            ah[mi][0] = *(const uint32_t*)(p0);
            ah[mi][1] = *(const uint32_t*)(p1);
            ah[mi][2] = *(const uint32_t*)(p0 + 16);
            ah[mi][3] = *(const uint32_t*)(p1 + 16);
            al[mi][0] = *(const uint32_t*)(p0 + PL);
            al[mi][1] = *(const uint32_t*)(p1 + PL);
            al[mi][2] = *(const uint32_t*)(p0 + PL + 16);
            al[mi][3] = *(const uint32_t*)(p1 + PL + 16);
        }
        uint32_t bh[8][2], bl[8][2];
#pragma unroll
        for (int ni = 0; ni < 8; ni++) {
            int nn = c0 + ni * 8 + gq;
            const char* pb = sm + bOff + nn * ASTR + (k0 + tq * 2) * 2;
            bh[ni][0] = *(const uint32_t*)(pb);
            bh[ni][1] = *(const uint32_t*)(pb + 16);
            bl[ni][0] = *(const uint32_t*)(pb + PL);
            bl[ni][1] = *(const uint32_t*)(pb + PL + 16);
        }
#pragma unroll
        for (int ni = 0; ni < 8; ni++) {
            mma_bf16(acc[0][ni], ah[0], bh[ni]);
            mma_bf16(acc[1][ni], ah[1], bh[ni]);
            mma_bf16(acc[0][ni], ah[0], bl[ni]);
            mma_bf16(acc[1][ni], ah[1], bl[ni]);
            mma_bf16(acc[0][ni], al[0], bh[ni]);
            mma_bf16(acc[1][ni], al[1], bh[ni]);
        }
    }
}

__device__ __forceinline__ void copy_planes(char* sm, int off,
                                            const __nv_bfloat16* hi,
                                            const __nv_bfloat16* lo, int tid) {
    const uint4* s0 = (const uint4*)hi;
    const uint4* s1 = (const uint4*)lo;
#pragma unroll
    for (int i = 0; i < 8; i++) {
        int idx = i * 256 + tid;   // 0..2047
        int row = idx >> 4;
        int q = idx & 15;
        *(uint4*)(sm + off + row * ASTR + q * 16) = s0[idx];
        *(uint4*)(sm + off + PL + row * ASTR + q * 16) = s1[idx];
    }
}

// ===========================================================================
// Fused GEMM0+GEMM1: g1 = ((x@W_in + b_in) @ W1) * dis  -> bf16 g_gb
// ===========================================================================
#define SMF_A  0
#define SMF_B0 (2 * PL)
#define SMF_B1 (4 * PL)
#define SMF_TOTAL (6 * PL)   // 208896

__global__ __launch_bounds__(256, 1)
void gemm01_kernel(const float* __restrict__ bias,
                   const float* __restrict__ dis,
                   __nv_bfloat16* __restrict__ outgb) {
    extern __shared__ char sm[];
    const int tid = threadIdx.x;
    const int row0 = blockIdx.x * 128;

    copy_planes(sm, SMF_A, g_pah + (size_t)row0 * 128, g_pal + (size_t)row0 * 128, tid);
    copy_planes(sm, SMF_B0, g_wh, g_wl, tid);
    copy_planes(sm, SMF_B1, g_wh + HH * HH, g_wl + HH * HH, tid);
    __syncthreads();

    const int w = tid >> 5;
    const int lane = tid & 31;
    const int gq = lane >> 2;
    const int tq = lane & 3;
    const int r0 = (w & 3) * 32;
    const int c0 = (w >> 2) * 64;

    float acc[2][8][4];
#pragma unroll
    for (int mi = 0; mi < 2; mi++)
#pragma unroll
        for (int ni = 0; ni < 8; ni++)
#pragma unroll
            for (int j = 0; j < 4; j++) acc[mi][ni][j] = 0.0f;

    mma_mainloop(sm, SMF_A, SMF_B0, r0, c0, gq, tq, acc);
    __syncthreads();   // all warps done reading A planes

    // T = acc + bias -> split into A planes (overwrite)
#pragma unroll
    for (int mi = 0; mi < 2; mi++) {
        int rr = r0 + mi * 16 + gq;
#pragma unroll
        for (int ni = 0; ni < 8; ni++) {
            int c = c0 + ni * 8 + tq * 2;
            float b0 = bias[c], b1 = bias[c + 1];
            uint32_t hi, lo;
            split2(acc[mi][ni][0] + b0, acc[mi][ni][1] + b1, hi, lo);
            *(uint32_t*)(sm + SMF_A + rr * ASTR + c * 2) = hi;
            *(uint32_t*)(sm + SMF_A + PL + rr * ASTR + c * 2) = lo;
            split2(acc[mi][ni][2] + b0, acc[mi][ni][3] + b1, hi, lo);
            *(uint32_t*)(sm + SMF_A + (rr + 8) * ASTR + c * 2) = hi;
            *(uint32_t*)(sm + SMF_A + PL + (rr + 8) * ASTR + c * 2) = lo;
        }
    }
    __syncthreads();

#pragma unroll
    for (int mi = 0; mi < 2; mi++)
#pragma unroll
        for (int ni = 0; ni < 8; ni++)
#pragma unroll
            for (int j = 0; j < 4; j++) acc[mi][ni][j] = 0.0f;

    mma_mainloop(sm, SMF_A, SMF_B1, r0, c0, gq, tq, acc);

#pragma unroll
    for (int mi = 0; mi < 2; mi++) {
        int r = row0 + r0 + mi * 16 + gq;
        float s0 = dis[r], s1 = dis[r + 8];
#pragma unroll
        for (int ni = 0; ni < 8; ni++) {
            int c = c0 + ni * 8 + tq * 2;
            ((uint32_t*)outgb)[((size_t)r * 128 + c) >> 1] =
                pack_bf2(acc[mi][ni][0] * s0, acc[mi][ni][1] * s0);
            ((uint32_t*)outgb)[((size_t)(r + 8) * 128 + c) >> 1] =
                pack_bf2(acc[mi][ni][2] * s1, acc[mi][ni][3] * s1);
        }
    }
}

// ===========================================================================
// Single GEMM (layer 2): g2 = (h1 @ W2) * dis -> bf16 g_gb
// ===========================================================================
#define SMG_A 0
#define SMG_B (2 * PL)
#define SMG_TOTAL (4 * PL)   // 139264

__global__ __launch_bounds__(256, 1)
void gemm_g_kernel(const __nv_bfloat16* __restrict__ Ah,
                   const __nv_bfloat16* __restrict__ Al,
                   const __nv_bfloat16* __restrict__ Wh,
                   const __nv_bfloat16* __restrict__ Wl,
                   const float* __restrict__ dis,
                   __nv_bfloat16* __restrict__ outgb) {
    extern __shared__ char sm[];
    const int tid = threadIdx.x;
    const int row0 = blockIdx.x * 128;

    copy_planes(sm, SMG_A, Ah + (size_t)row0 * 128, Al + (size_t)row0 * 128, tid);
    copy_planes(sm, SMG_B, Wh, Wl, tid);
    __syncthreads();

    const int w = tid >> 5;
    const int lane = tid & 31;
    const int gq = lane >> 2;
    const int tq = lane & 3;
    const int r0 = (w & 3) * 32;
    const int c0 = (w >> 2) * 64;

    float acc[2][8][4];
#pragma unroll
    for (int mi = 0; mi < 2; mi++)
#pragma unroll
        for (int ni = 0; ni < 8; ni++)
#pragma unroll
            for (int j = 0; j < 4; j++) acc[mi][ni][j] = 0.0f;

    mma_mainloop(sm, SMG_A, SMG_B, r0, c0, gq, tq, acc);

#pragma unroll
    for (int mi = 0; mi < 2; mi++) {
        int r = row0 + r0 + mi * 16 + gq;
        float s0 = dis[r], s1 = dis[r + 8];
#pragma unroll
        for (int ni = 0; ni < 8; ni++) {
            int c = c0 + ni * 8 + tq * 2;
            ((uint32_t*)outgb)[((size_t)r * 128 + c) >> 1] =
                pack_bf2(acc[mi][ni][0] * s0, acc[mi][ni][1] * s0);
            ((uint32_t*)outgb)[((size_t)(r + 8) * 128 + c) >> 1] =
                pack_bf2(acc[mi][ni][2] * s1, acc[mi][ni][3] * s1);
        }
    }
}

// ===========================================================================
// Shared gather core: one warp per node, f32 accumulate of bf16 g rows.
// ===========================================================================
__device__ __forceinline__ float4 gather_core(int w, int lane, const float* b) {
    int beg = g_rowptr[w];
    int end = g_rowptr[w + 1];

    const uint2* G = (const uint2*)g_gb;
    float4 a0, a1 = make_float4(0.f, 0.f, 0.f, 0.f);
    {
        uint2 sv = G[(size_t)w * 32 + lane];   // self term
        float2 f0 = unpack_bf2(sv.x), f1 = unpack_bf2(sv.y);
        a0 = make_float4(f0.x, f0.y, f1.x, f1.y);
    }

    int e = beg;
    while (e < end) {
        int cnt = min(end - e, 32);
        int c = (lane < cnt) ? g_col[e + lane] : 0;
        int i = 0;
        for (; i + 8 <= cnt; i += 8) {
            int s0 = __shfl_sync(0xffffffffu, c, i);
            int s1 = __shfl_sync(0xffffffffu, c, i + 1);
            int s2 = __shfl_sync(0xffffffffu, c, i + 2);
            int s3 = __shfl_sync(0xffffffffu, c, i + 3);
            int s4 = __shfl_sync(0xffffffffu, c, i + 4);
            int s5 = __shfl_sync(0xffffffffu, c, i + 5);
            int s6 = __shfl_sync(0xffffffffu, c, i + 6);
            int s7 = __shfl_sync(0xffffffffu, c, i + 7);
            uint2 v0 = G[(size_t)s0 * 32 + lane];
            uint2 v1 = G[(size_t)s1 * 32 + lane];
            uint2 v2 = G[(size_t)s2 * 32 + lane];
            uint2 v3 = G[(size_t)s3 * 32 + lane];
            uint2 v4 = G[(size_t)s4 * 32 + lane];
            uint2 v5 = G[(size_t)s5 * 32 + lane];
            uint2 v6 = G[(size_t)s6 * 32 + lane];
            uint2 v7 = G[(size_t)s7 * 32 + lane];
            float2 f;
            f = unpack_bf2(v0.x); a0.x += f.x; a0.y += f.y;
            f = unpack_bf2(v0.y); a0.z += f.x; a0.w += f.y;
            f = unpack_bf2(v1.x); a1.x += f.x; a1.y += f.y;
            f = unpack_bf2(v1.y); a1.z += f.x; a1.w += f.y;
            f = unpack_bf2(v2.x); a0.x += f.x; a0.y += f.y;
            f = unpack_bf2(v2.y); a0.z += f.x; a0.w += f.y;
            f = unpack_bf2(v3.x); a1.x += f.x; a1.y += f.y;
            f = unpack_bf2(v3.y); a1.z += f.x; a1.w += f.y;
            f = unpack_bf2(v4.x); a0.x += f.x; a0.y += f.y;
            f = unpack_bf2(v4.y); a0.z += f.x; a0.w += f.y;
            f = unpack_bf2(v5.x); a1.x += f.x; a1.y += f.y;
            f = unpack_bf2(v5.y); a1.z += f.x; a1.w += f.y;
            f = unpack_bf2(v6.x); a0.x += f.x; a0.y += f.y;
            f = unpack_bf2(v6.y); a0.z += f.x; a0.w += f.y;
            f = unpack_bf2(v7.x); a1.x += f.x; a1.y += f.y;
            f = unpack_bf2(v7.y); a1.z += f.x; a1.w += f.y;
        }
        for (; i + 4 <= cnt; i += 4) {
            int s0 = __shfl_sync(0xffffffffu, c, i);
            int s1 = __shfl_sync(0xffffffffu, c, i + 1);
            int s2 = __shfl_sync(0xffffffffu, c, i + 2);
            int s3 = __shfl_sync(0xffffffffu, c, i + 3);
            uint2 v0 = G[(size_t)s0 * 32 + lane];
            uint2 v1 = G[(size_t)s1 * 32 + lane];
            uint2 v2 = G[(size_t)s2 * 32 + lane];
            uint2 v3 = G[(size_t)s3 * 32 + lane];
            float2 f;
            f = unpack_bf2(v0.x); a0.x += f.x; a0.y += f.y;
            f = unpack_bf2(v0.y); a0.z += f.x; a0.w += f.y;
            f = unpack_bf2(v1.x); a1.x += f.x; a1.y += f.y;
            f = unpack_bf2(v1.y); a1.z += f.x; a1.w += f.y;
            f = unpack_bf2(v2.x); a0.x += f.x; a0.y += f.y;
            f = unpack_bf2(v2.y); a0.z += f.x; a0.w += f.y;
            f = unpack_bf2(v3.x); a1.x += f.x; a1.y += f.y;
            f = unpack_bf2(v3.y); a1.z += f.x; a1.w += f.y;
        }
        for (; i < cnt; i++) {
            int s0 = __shfl_sync(0xffffffffu, c, i);
            uint2 v0 = G[(size_t)s0 * 32 + lane];
            float2 f;
            f = unpack_bf2(v0.x); a0.x += f.x; a0.y += f.y;
            f = unpack_bf2(v0.y); a0.z += f.x; a0.w += f.y;
        }
        e += cnt;
    }
    a0.x += a1.x; a0.y += a1.y; a0.z += a1.z; a0.w += a1.w;

    float sc = g_dis[w];
    float4 bb = *(const float4*)(b + lane * 4);
    float4 o;
    o.x = fmaxf(fmaf(sc, a0.x, bb.x), 0.0f);
    o.y = fmaxf(fmaf(sc, a0.y, bb.y), 0.0f);
    o.z = fmaxf(fmaf(sc, a0.z, bb.z), 0.0f);
    o.w = fmaxf(fmaf(sc, a0.w, bb.w), 0.0f);
    return o;
}

// Layer-1 gather: write h1 as bf16 hi/lo planes.
__global__ void gather_kernel(const float* __restrict__ b,
                              __nv_bfloat16* __restrict__ outh,
                              __nv_bfloat16* __restrict__ outl) {
    int w = (blockIdx.x * blockDim.x + threadIdx.x) >> 5;
    if (w >= NN) return;
    int lane = threadIdx.x & 31;
    float4 o = gather_core(w, lane, b);
    uint32_t h0, l0, h1, l1;
    split2(o.x, o.y, h0, l0);
    split2(o.z, o.w, h1, l1);
    ((uint2*)outh)[(size_t)w * 32 + lane] = make_uint2(h0, h1);
    ((uint2*)outl)[(size_t)w * 32 + lane] = make_uint2(l0, l1);
}

// Layer-2 gather fused with mean-pool accumulation. 512 thr = 16 nodes/block.
__global__ __launch_bounds__(512)
void gather_pool_kernel(const float* __restrict__ b,
                        const int* __restrict__ batch) {
    __shared__ float s[GG * HH];
    __shared__ float cnt[GG];
    int tid = threadIdx.x;
    for (int i = tid; i < GG * HH; i += 512) s[i] = 0.0f;
    if (tid < GG) cnt[tid] = 0.0f;
    __syncthreads();

    int w = (blockIdx.x * 512 + tid) >> 5;   // grid covers NN exactly (2500*16)
    int lane = tid & 31;
    if (w < NN) {
        float4 o = gather_core(w, lane, b);
        int bg = batch[w];
        float* sp = s + bg * HH + lane * 4;
        atomicAdd(sp + 0, o.x);
        atomicAdd(sp + 1, o.y);
        atomicAdd(sp + 2, o.z);
        atomicAdd(sp + 3, o.w);
        if (lane == 0) atomicAdd(&cnt[bg], 1.0f);
    }
    __syncthreads();

    int n0 = blockIdx.x * 16;
    if (n0 < NN) {
        int n1 = min(n0 + 15, NN - 1);
        int b0 = batch[n0], b1 = batch[n1];
        for (int bg = b0; bg <= b1; bg++) {
            if (tid < HH) atomicAdd(&g_pool[bg * HH + tid], s[bg * HH + tid]);
            if (tid == 0) atomicAdd(&g_pool[GG * HH + bg], cnt[bg]);
        }
    }
}

// ===========================================================================
// Head
// ===========================================================================
__global__ void head_kernel(const float* __restrict__ Wf1,
                            const float* __restrict__ bf1,
                            const float* __restrict__ Wf2,
                            const float* __restrict__ bf2,
                            float* __restrict__ out) {
    __shared__ float P[GG * HH];
    __shared__ float Z[GG * 64];
    int tid = threadIdx.x;

    for (int i = tid; i < GG * HH; i += 1024) {
        float c = g_pool[GG * HH + i / HH];
        P[i] = g_pool[i] / fmaxf(c, 1.0f);
    }
    __syncthreads();

    {
        int g = tid >> 6;
        int j = tid & 63;
        float acc = bf1[j];
        const float* p = P + g * HH;
#pragma unroll 8
        for (int k = 0; k < HH; k++) acc += p[k] * Wf1[k * 64 + j];
        Z[g * 64 + j] = fmaxf(acc, 0.0f);
    }
    __syncthreads();

    if (tid < GG * CC) {
        int g = tid / CC;
        int c = tid % CC;
        float acc = bf2[c];
        const float* z = Z + g * 64;
#pragma unroll
        for (int j = 0; j < 64; j++) acc += z[j] * Wf2[j * CC + c];
        out[g * CC + c] = acc;
    }
}

// ===========================================================================
extern "C" void kernel_launch(void* const* d_in, const int* in_sizes, int n_in,
                              void* d_out, int out_size) {
    const float* x = (const float*)d_in[0];
    const int* edge = (const int*)d_in[1];     // int32
    const int* batch = (const int*)d_in[2];    // int32
    const float* W_in = (const float*)d_in[3];
    const float* b_in = (const float*)d_in[4];
    const float* W1 = (const float*)d_in[5];
    const float* b1 = (const float*)d_in[6];
    const float* W2 = (const float*)d_in[7];
    const float* b2 = (const float*)d_in[8];
    const float* Wf1 = (const float*)d_in[9];
    const float* bf1 = (const float*)d_in[10];
    const float* Wf2 = (const float*)d_in[11];
    const float* bf2 = (const float*)d_in[12];
    float* out = (float*)d_out;

    const int* src = edge;
    const int* dst = edge + EE;

    void *p_deg, *p_pool, *p_gb, *p_dis, *p_pah, *p_pal, *p_wh, *p_wl;
    cudaGetSymbolAddress(&p_deg, g_deg);
    cudaGetSymbolAddress(&p_pool, g_pool);
    cudaGetSymbolAddress(&p_gb, g_gb);
    cudaGetSymbolAddress(&p_dis, g_dis);
    cudaGetSymbolAddress(&p_pah, g_pah);
    cudaGetSymbolAddress(&p_pal, g_pal);
    cudaGetSymbolAddress(&p_wh, g_wh);
    cudaGetSymbolAddress(&p_wl, g_wl);
    __nv_bfloat16* pah = (__nv_bfloat16*)p_pah;
    __nv_bfloat16* pal = (__nv_bfloat16*)p_pal;
    __nv_bfloat16* wh = (__nv_bfloat16*)p_wh;
    __nv_bfloat16* wl = (__nv_bfloat16*)p_wl;
    __nv_bfloat16* gb = (__nv_bfloat16*)p_gb;

    cudaFuncSetAttribute(gemm01_kernel, cudaFuncAttributeMaxDynamicSharedMemorySize, SMF_TOTAL);
    cudaFuncSetAttribute(gemm_g_kernel, cudaFuncAttributeMaxDynamicSharedMemorySize, SMG_TOTAL);

    const int gemmGrid = NP / 128;  // 313

    // 1-4: minimal deps for gemm01 (memset, deg, conv, dis)
    cudaMemsetAsync(p_deg, 0, NN * sizeof(int));                   // 1
    deg_kernel<<<(EE / 4 + 255) / 256, 256>>>(dst);                // 2
    conv_xw_kernel<<<XBLKS + 192, 256>>>(x, W_in, W1, W2);         // 3
    dis_kernel<<<(NN + 1023) / 1024, 1024>>>();                    // 4

    // 5: fused layer0+1 GEMM (profiled slot)
    gemm01_kernel<<<gemmGrid, 256, SMF_TOTAL>>>(b_in, (const float*)p_dis, gb);  // 5

    // CSR finish
    scan1_kernel<<<40, 1024>>>();                                  // 6
    scan3_kernel<<<40, 1024>>>();                                  // 7
    fill_kernel<<<(EE / 4 + 255) / 256, 256>>>(src, dst);          // 8

    // Layer 1 gather -> h1 planes
    gather_kernel<<<(NN * 32 + 255) / 256, 256>>>(b1, pah, pal);   // 9

    // Layer 2: g2 = (h1 @ W2) * dis
    gemm_g_kernel<<<gemmGrid, 256, SMG_TOTAL>>>(pah, pal, wh + 2 * HH * HH, wl + 2 * HH * HH,
                                                (const float*)p_dis, gb);        // 10

    // Layer 2 gather fused with pool
    cudaMemsetAsync(p_pool, 0, (GG * HH + GG) * sizeof(float));    // 11
    gather_pool_kernel<<<(NN * 32 + 511) / 512, 512>>>(b2, batch); // 12
    head_kernel<<<1, 1024>>>(Wf1, bf1, Wf2, bf2, out);             // 13
}